// round 11
// baseline (speedup 1.0000x reference)
#include <cuda_runtime.h>

#define BATCH 4
#define NPT   8192
#define KNB   9
#define CH    7
#define NPTS  (BATCH*NPT)      // 32768
#define NROWS (NPTS*KNB)       // 294912
#define LOGCAP 128             // per-query insert log capacity (ring-order expected ~20)

#define G     32               // grid cells per dim
#define GC    (G*G*G)          // 32768 cells per batch
#define TC    (BATCH*GC)       // 131072 total cells
#define BOXLO (-6.0f)
#define CS    0.375f           // 12/32
#define INV_CS (1.0f/0.375f)

typedef unsigned long long ull;

// ---------------- device scratch (no allocations allowed) ----------------
__device__ int    g_cnt[TC];                    // per-cell point counts
__device__ int    g_cstart[TC];                 // per-cell start offsets (global)
__device__ int    g_cur[TC];                    // fill cursors
__device__ int    g_part[1024];                 // scan partials
__device__ int    g_pcid[NPTS];                 // point -> cell id
__device__ float4 g_pts4[NPTS];                 // cell-sorted points: (x,y,z, idx_bits)
__device__ float2 g_log[(size_t)NPTS*LOGCAP];   // insert log: (dist, idx-bits)
__device__ int    g_lcnt[NPTS];                 // log counts
__device__ float  g_pd[NPTS*KNB];               // top-9 distances (sorted asc)
__device__ float4 g_h[NROWS*2];                 // hidden activations, 8 floats/row
__device__ float  g_sum1[CH], g_sq1[CH];        // BN1 accumulators
__device__ float  g_sum2[CH], g_sq2[CH];        // BN2 accumulators

#define INF_F (__int_as_float(0x7f800000))

// insert d into sorted-ascending dist[KNB], popping the max; pure FMNMX chain
__device__ __forceinline__ void dchain(float* dist, float d) {
    float hd = d;
#pragma unroll
    for (int j = 0; j < KNB; ++j) {
        float lo = fminf(hd, dist[j]);
        hd = fmaxf(hd, dist[j]);
        dist[j] = lo;
    }
}

__device__ __forceinline__ int cellc(float v) {
    int c = __float2int_rd((v - BOXLO) * INV_CS);
    return min(max(c, 0), G - 1);
}

// ---------------- grid build ----------------
__global__ void __launch_bounds__(256) k_zero() {
    int i = blockIdx.x * 256 + threadIdx.x;
    if (i < TC) g_cnt[i] = 0;
    if (i < CH) { g_sum1[i] = 0.f; g_sq1[i] = 0.f; g_sum2[i] = 0.f; g_sq2[i] = 0.f; }
}

__global__ void __launch_bounds__(256) k_count(const float* __restrict__ x) {
    const int p = blockIdx.x * 256 + threadIdx.x;        // global point id
    float px = x[3*p], py = x[3*p+1], pz = x[3*p+2];
    int cid = (p >> 13) * GC + (cellc(pz) * G + cellc(py)) * G + cellc(px);
    g_pcid[p] = cid;
    atomicAdd(&g_cnt[cid], 1);
}

__global__ void __launch_bounds__(256) k_scanA() {     // 4 blocks: 1024 chunks of 128
    const int j = blockIdx.x * 256 + threadIdx.x;
    int s = 0;
#pragma unroll 4
    for (int i = 0; i < TC/1024; ++i) s += g_cnt[j * (TC/1024) + i];
    g_part[j] = s;
}

__global__ void __launch_bounds__(1024) k_scanB() {    // 1 block: scan partials + writeback
    __shared__ int sm[1024];
    const int t = threadIdx.x;
    int v = g_part[t];
    sm[t] = v;
    __syncthreads();
#pragma unroll
    for (int off = 1; off < 1024; off <<= 1) {
        int add = (t >= off) ? sm[t - off] : 0;
        __syncthreads();
        sm[t] += add;
        __syncthreads();
    }
    int base = sm[t] - v;    // exclusive prefix of this chunk
    int run = base;
    for (int i = 0; i < TC/1024; ++i) {
        int cid = t * (TC/1024) + i;
        g_cstart[cid] = run;
        g_cur[cid] = run;
        run += g_cnt[cid];
    }
}

__global__ void __launch_bounds__(256) k_fill(const float* __restrict__ x) {
    const int p = blockIdx.x * 256 + threadIdx.x;
    const int n = p & (NPT - 1);                          // within-batch index
    int cid = g_pcid[p];
    int slot = atomicAdd(&g_cur[cid], 1);
    g_pts4[slot] = make_float4(x[3*p], x[3*p+1], x[3*p+2], __int_as_float(n));
}

// ---------------- kernel: grid 9-NN with ring expansion ----------------
__global__ void __launch_bounds__(256) knn_grid() {
    const int s = blockIdx.x * 256 + threadIdx.x;        // cell-sorted slot (batches contiguous)
    const int b = s >> 13;
    float4 me = g_pts4[s];
    const float qx = me.x, qy = me.y, qz = me.z;
    const int n = __float_as_int(me.w);
    const float ax = -2.0f * qx, ay = -2.0f * qy, az = -2.0f * qz;
    const float qsq = fmaf(qx, qx, fmaf(qy, qy, qz * qz));

    const int cx = cellc(qx), cy = cellc(qy), cz = cellc(qz);
    const int cb = b * GC;

    float dist[KNB];
#pragma unroll
    for (int j = 0; j < KNB; ++j) dist[j] = INF_F;
    float thr = INF_F;
    int cnt = 0;
    const int p = b * NPT + n;
    float2* lg = g_log + (size_t)p * LOGCAP;

    bool done = false;
    for (int r = 0; r <= G && !done; ++r) {
        // scan shell L_inf == r
        for (int dz = -r; dz <= r; ++dz) {
            int zc = cz + dz;
            if (zc < 0 || zc >= G) continue;
            bool zface = (dz == -r || dz == r);
            for (int dy = -r; dy <= r; ++dy) {
                int yc = cy + dy;
                if (yc < 0 || yc >= G) continue;
                bool yface = (dy == -r || dy == r);
                int dxstep = (zface || yface || r == 0) ? 1 : 2 * r;
                for (int dx = -r; dx <= r; dx += dxstep) {
                    int xc = cx + dx;
                    if (xc < 0 || xc >= G) continue;
                    int cid = cb + (zc * G + yc) * G + xc;
                    int st = g_cstart[cid];
                    int en = st + g_cnt[cid];
                    for (int i = st; i < en; ++i) {
                        float4 c = g_pts4[i];
                        // d = |c|^2 - 2 q.c  ==  c.(c - 2q)
                        float d = fmaf(c.z, c.z + az,
                                  fmaf(c.y, c.y + ay,
                                       c.x * (c.x + ax)));
                        int mi = __float_as_int(c.w);
                        if (d < thr && mi != n) {
                            int w = (cnt < LOGCAP) ? cnt : (LOGCAP - 1);
                            lg[w] = make_float2(d, c.w);
                            ++cnt;
                            dchain(dist, d);
                            thr = dist[KNB-1];
                        }
                    }
                }
            }
        }
        // termination bound: 9 found AND 9th ball inside scanned box
        if (dist[KNB-1] < INF_F) {
            float face = INF_F;
            if (cx - r > 0)     face = fminf(face, qx - (BOXLO + (cx - r) * CS));
            if (cx + r < G - 1) face = fminf(face, (BOXLO + (cx + r + 1) * CS) - qx);
            if (cy - r > 0)     face = fminf(face, qy - (BOXLO + (cy - r) * CS));
            if (cy + r < G - 1) face = fminf(face, (BOXLO + (cy + r + 1) * CS) - qy);
            if (cz - r > 0)     face = fminf(face, qz - (BOXLO + (cz - r) * CS));
            if (cz + r < G - 1) face = fminf(face, (BOXLO + (cz + r + 1) * CS) - qz);
            float d9sq = dist[KNB-1] + qsq;           // squared Euclid of 9th
            if (d9sq + 1.0e-4f <= face * face) done = true;
        }
    }

    g_lcnt[p] = (cnt < LOGCAP) ? cnt : LOGCAP;
#pragma unroll
    for (int j = 0; j < KNB; ++j) g_pd[p * KNB + j] = dist[j];
}

// ---------------- block reduction of 14 partial sums -> global atomics ----------------
__device__ __forceinline__ void block_reduce_14(float* v, float* dst1, float* dst2) {
    __shared__ float red[8 * 14];
    const int lane = threadIdx.x & 31, w = threadIdx.x >> 5;
#pragma unroll
    for (int i = 0; i < 14; ++i) {
        float t = v[i];
        t += __shfl_down_sync(0xffffffffu, t, 16);
        t += __shfl_down_sync(0xffffffffu, t, 8);
        t += __shfl_down_sync(0xffffffffu, t, 4);
        t += __shfl_down_sync(0xffffffffu, t, 2);
        t += __shfl_down_sync(0xffffffffu, t, 1);
        v[i] = t;
    }
    if (lane == 0) {
#pragma unroll
        for (int i = 0; i < 14; ++i) red[w * 14 + i] = v[i];
    }
    __syncthreads();
    if (threadIdx.x < 14) {
        float t = 0.f;
#pragma unroll
        for (int ww = 0; ww < 8; ++ww) t += red[ww * 14 + threadIdx.x];
        if (threadIdx.x < CH) atomicAdd(&dst1[threadIdx.x], t);
        else                  atomicAdd(&dst2[threadIdx.x - CH], t);
    }
}

// ---------------- kernel: index claim + features + MLP1 + BN1 stats --------
__global__ void __launch_bounds__(256) feat_kernel(const float* __restrict__ x,
                                                   const float* __restrict__ w1) {
    __shared__ float w1s[CH * CH];
    if (threadIdx.x < CH * CH) w1s[threadIdx.x] = w1[threadIdx.x];
    __syncthreads();

    const int p = blockIdx.x * 256 + threadIdx.x;     // 0..NPTS-1
    const int b = p >> 13;
    const int n = p & (NPT - 1);

    float dm[KNB];
#pragma unroll
    for (int j = 0; j < KNB; ++j) dm[j] = g_pd[p * KNB + j];

    // claim indices: every final top-9 value was logged (same < gate); leftmost-unclaimed-equal
    int idx[KNB];
#pragma unroll
    for (int j = 0; j < KNB; ++j) idx[j] = n;         // safe default
    unsigned claimed = 0;
    const float dmax = dm[KNB-1];
    const float2* L = g_log + (size_t)p * LOGCAP;
    const int cn = g_lcnt[p];
    for (int k = 0; k < cn; ++k) {
        float2 e = L[k];
        if (e.x <= dmax) {
            bool donec = false;
#pragma unroll
            for (int j = 0; j < KNB; ++j) {
                bool m = (!donec) && (dm[j] == e.x) && !((claimed >> j) & 1u);
                if (m) { idx[j] = __float_as_int(e.y); claimed |= (1u << j); donec = true; }
            }
        }
    }

    const float* xb = x + b * (NPT * 3);
    const float qx = xb[3*n], qy = xb[3*n+1], qz = xb[3*n+2];

    float vx[KNB], vy[KNB], vz[KNB], ph[KNB];
#pragma unroll
    for (int j = 0; j < KNB; ++j) {
        int mi = idx[j];
        vx[j] = xb[3*mi]   - qx;
        vy[j] = xb[3*mi+1] - qy;
        vz[j] = xb[3*mi+2] - qz;
        ph[j] = atan2f(vy[j], vx[j]);   // monotone in reference's phi
    }
    // stable unrolled insertion sort by phi ascending (registers only)
#pragma unroll
    for (int i = 1; i < KNB; ++i)
#pragma unroll
        for (int j = i; j > 0; --j)
            if (ph[j] < ph[j-1]) {
                float t;
                t = ph[j]; ph[j] = ph[j-1]; ph[j-1] = t;
                t = vx[j]; vx[j] = vx[j-1]; vx[j-1] = t;
                t = vy[j]; vy[j] = vy[j-1]; vy[j-1] = t;
                t = vz[j]; vz[j] = vz[j-1]; vz[j-1] = t;
            }

    float mask = 1.0f;
    float vals[2 * CH];
#pragma unroll
    for (int i = 0; i < 2 * CH; ++i) vals[i] = 0.f;

#pragma unroll
    for (int j = 0; j < KNB; ++j) {
        const int j2 = (j + 1 == KNB) ? 0 : (j + 1);
        float axv = vx[j],  ayv = vy[j],  azv = vz[j];
        float bxv = vx[j2], byv = vy[j2], bzv = vz[j2];
        float cx = 0.5f * (axv + bxv), cy = 0.5f * (ayv + byv), cz = 0.5f * (azv + bzv);
        float nx = fmaf(ayv, bzv, -azv * byv) + 1e-5f;
        float ny = fmaf(azv, bxv, -axv * bzv) + 1e-5f;
        float nz = fmaf(axv, byv, -ayv * bxv) + 1e-5f;
        float inv = rsqrtf(fmaf(nx, nx, fmaf(ny, ny, nz * nz)));
        nx *= inv; ny *= inv; nz *= inv;
        if (j == 0) mask = (nx > 0.f) ? 1.f : -1.f;
        nx *= mask; ny *= mask; nz *= mask;
        float pos = fmaf(cx, nx, fmaf(cy, ny, cz * nz)) * 0.57735026918962576f; // /sqrt(3)
        float f[CH] = {cx, cy, cz, nx, ny, nz, pos};
        float h[CH];
#pragma unroll
        for (int o = 0; o < CH; ++o) {
            float acc = 0.f;
#pragma unroll
            for (int c = 0; c < CH; ++c) acc = fmaf(f[c], w1s[o * CH + c], acc);
            h[o] = acc;
            vals[o] += acc;
            vals[CH + o] = fmaf(acc, acc, vals[CH + o]);
        }
        const int r = p * KNB + j;
        g_h[2*r]     = make_float4(h[0], h[1], h[2], h[3]);
        g_h[2*r + 1] = make_float4(h[4], h[5], h[6], 0.f);
    }
    block_reduce_14(vals, g_sum1, g_sq1);
}

// ---------------- relu(bn1) -> MLP2 (+bias) in place, BN2 stats ----------
__global__ void __launch_bounds__(256) mlp2_kernel(const float* __restrict__ w2,
                                                   const float* __restrict__ bias2,
                                                   const float* __restrict__ gamma1,
                                                   const float* __restrict__ beta1) {
    __shared__ float w2s[CH * CH], cb[CH], aff[2 * CH];
    const int t = threadIdx.x;
    if (t < CH * CH) w2s[t] = w2[t];
    if (t < CH)      cb[t]  = bias2[t];
    if (t < CH) {
        const float invN = 1.0f / (float)NROWS;
        float m = g_sum1[t] * invN;
        float v = g_sq1[t] * invN - m * m;
        float sc = gamma1[t] * rsqrtf(v + 1e-5f);
        aff[t] = sc;
        aff[CH + t] = fmaf(-m, sc, beta1[t]);
    }
    __syncthreads();

    const int r = blockIdx.x * 256 + t;    // < NROWS (exact)
    float4 h0 = g_h[2*r], h1 = g_h[2*r + 1];
    float hv[CH] = {h0.x, h0.y, h0.z, h0.w, h1.x, h1.y, h1.z};
    float a[CH];
#pragma unroll
    for (int c = 0; c < CH; ++c) a[c] = fmaxf(fmaf(hv[c], aff[c], aff[CH + c]), 0.f);
    float vals[2 * CH];
#pragma unroll
    for (int o = 0; o < CH; ++o) {
        float acc = cb[o];
#pragma unroll
        for (int c = 0; c < CH; ++c) acc = fmaf(a[c], w2s[o * CH + c], acc);
        vals[o] = acc;
        vals[CH + o] = acc * acc;
    }
    g_h[2*r]     = make_float4(vals[0], vals[1], vals[2], vals[3]);
    g_h[2*r + 1] = make_float4(vals[4], vals[5], vals[6], 0.f);
    block_reduce_14(vals, g_sum2, g_sq2);
}

// ---------------- relu(bn2) -> MLP3 (+bias) -> max over K -> concat -------
__global__ void __launch_bounds__(256) out_kernel(const float* __restrict__ x,
                                                  const float* __restrict__ w3,
                                                  const float* __restrict__ bias3,
                                                  const float* __restrict__ gamma2,
                                                  const float* __restrict__ beta2,
                                                  float* __restrict__ out) {
    __shared__ float w3s[CH * CH], cb[CH], aff[2 * CH];
    const int t = threadIdx.x;
    if (t < CH * CH) w3s[t] = w3[t];
    if (t < CH)      cb[t]  = bias3[t];
    if (t < CH) {
        const float invN = 1.0f / (float)NROWS;
        float m = g_sum2[t] * invN;
        float v = g_sq2[t] * invN - m * m;
        float sc = gamma2[t] * rsqrtf(v + 1e-5f);
        aff[t] = sc;
        aff[CH + t] = fmaf(-m, sc, beta2[t]);
    }
    __syncthreads();

    const int p = blockIdx.x * 256 + t;    // point id
    float best[CH];
#pragma unroll
    for (int o = 0; o < CH; ++o) best[o] = -INF_F;

#pragma unroll
    for (int j = 0; j < KNB; ++j) {
        const int r = p * KNB + j;
        float4 h0 = g_h[2*r], h1 = g_h[2*r + 1];
        float hv[CH] = {h0.x, h0.y, h0.z, h0.w, h1.x, h1.y, h1.z};
        float a[CH];
#pragma unroll
        for (int c = 0; c < CH; ++c) a[c] = fmaxf(fmaf(hv[c], aff[c], aff[CH + c]), 0.f);
#pragma unroll
        for (int o = 0; o < CH; ++o) {
            float acc = cb[o];
#pragma unroll
            for (int c = 0; c < CH; ++c) acc = fmaf(a[c], w3s[o * CH + c], acc);
            best[o] = fmaxf(best[o], acc);
        }
    }
    float* orow = out + p * 10;
    orow[0] = x[p*3]; orow[1] = x[p*3+1]; orow[2] = x[p*3+2];
#pragma unroll
    for (int o = 0; o < CH; ++o) orow[3 + o] = best[o];
}

// ---------------- launch ----------------
extern "C" void kernel_launch(void* const* d_in, const int* in_sizes, int n_in,
                              void* d_out, int out_size) {
    const float* x      = (const float*)d_in[0];
    const float* w1     = (const float*)d_in[1];
    const float* gamma1 = (const float*)d_in[2];
    const float* beta1  = (const float*)d_in[3];
    const float* w2     = (const float*)d_in[4];
    const float* bias2  = (const float*)d_in[5];
    const float* gamma2 = (const float*)d_in[6];
    const float* beta2  = (const float*)d_in[7];
    const float* w3     = (const float*)d_in[8];
    const float* bias3  = (const float*)d_in[9];
    float* out = (float*)d_out;

    k_zero<<<(TC + 255) / 256, 256>>>();
    k_count<<<NPTS / 256, 256>>>(x);
    k_scanA<<<4, 256>>>();
    k_scanB<<<1, 1024>>>();
    k_fill<<<NPTS / 256, 256>>>(x);
    knn_grid<<<NPTS / 256, 256>>>();
    feat_kernel<<<NPTS / 256, 256>>>(x, w1);
    mlp2_kernel<<<NROWS / 256, 256>>>(w2, bias2, gamma1, beta1);
    out_kernel<<<NPTS / 256, 256>>>(x, w3, bias3, gamma2, beta2, out);
}

// round 12
// speedup vs baseline: 1.7107x; 1.7107x over previous
#include <cuda_runtime.h>

#define BATCH 4
#define NPT   8192
#define KNB   9
#define CH    7
#define NPTS  (BATCH*NPT)      // 32768
#define NROWS (NPTS*KNB)       // 294912
#define LOGCAP 128             // per-query insert log capacity

#define G     32               // grid cells per dim
#define GC    (G*G*G)          // 32768 cells per batch
#define TC    (BATCH*GC)       // 131072 total cells
#define NSCB  512              // scan blocks (TC/256)
#define BOXLO (-6.0f)
#define CS    0.375f           // 12/32
#define INV_CS (1.0f/0.375f)

typedef unsigned long long ull;

// ---------------- device scratch (no allocations allowed) ----------------
__device__ int    g_cnt[TC];                    // per-cell point counts
__device__ int    g_cstart[TC];                 // per-cell start offsets (global)
__device__ int    g_cur[TC];                    // fill cursors
__device__ int    g_part[NSCB];                 // scan partials
__device__ int    g_pcid[NPTS];                 // point -> cell id
__device__ float4 g_pts4[NPTS];                 // cell-sorted points: (x,y,z, idx_bits)
__device__ float2 g_log[(size_t)NPTS*LOGCAP];   // insert log: (dist, idx-bits)
__device__ int    g_lcnt[NPTS];                 // log counts
__device__ float  g_pd[NPTS*KNB];               // top-9 distances (sorted asc)
__device__ float4 g_h[NROWS*2];                 // hidden activations, 8 floats/row
__device__ float  g_sum1[CH], g_sq1[CH];        // BN1 accumulators
__device__ float  g_sum2[CH], g_sq2[CH];        // BN2 accumulators

#define INF_F (__int_as_float(0x7f800000))

// insert d into sorted-ascending dist[KNB], popping the max; pure FMNMX chain
__device__ __forceinline__ void dchain(float* dist, float d) {
    float hd = d;
#pragma unroll
    for (int j = 0; j < KNB; ++j) {
        float lo = fminf(hd, dist[j]);
        hd = fmaxf(hd, dist[j]);
        dist[j] = lo;
    }
}

__device__ __forceinline__ int cellc(float v) {
    int c = __float2int_rd((v - BOXLO) * INV_CS);
    return min(max(c, 0), G - 1);
}

// ---------------- grid build ----------------
__global__ void __launch_bounds__(256) k_zero() {
    int i = blockIdx.x * 256 + threadIdx.x;
    if (i < TC) g_cnt[i] = 0;
    if (i < CH) { g_sum1[i] = 0.f; g_sq1[i] = 0.f; g_sum2[i] = 0.f; g_sq2[i] = 0.f; }
}

__global__ void __launch_bounds__(256) k_count(const float* __restrict__ x) {
    const int p = blockIdx.x * 256 + threadIdx.x;        // global point id
    float px = x[3*p], py = x[3*p+1], pz = x[3*p+2];
    int cid = (p >> 13) * GC + (cellc(pz) * G + cellc(py)) * G + cellc(px);
    g_pcid[p] = cid;
    atomicAdd(&g_cnt[cid], 1);
}

// --- parallel 3-level exclusive scan of g_cnt -> g_cstart ---
__global__ void __launch_bounds__(256) k_scanA() {     // per-block scan of 256 cells
    __shared__ int sm[256];
    const int t = threadIdx.x;
    const int i = blockIdx.x * 256 + t;
    int v = g_cnt[i];
    sm[t] = v;
    __syncthreads();
#pragma unroll
    for (int off = 1; off < 256; off <<= 1) {
        int add = (t >= off) ? sm[t - off] : 0;
        __syncthreads();
        sm[t] += add;
        __syncthreads();
    }
    g_cstart[i] = sm[t] - v;                 // local exclusive prefix
    if (t == 255) g_part[blockIdx.x] = sm[t];
}

__global__ void __launch_bounds__(NSCB) k_scanB() {    // scan the 512 block sums
    __shared__ int sm[NSCB];
    const int t = threadIdx.x;
    int v = g_part[t];
    sm[t] = v;
    __syncthreads();
#pragma unroll
    for (int off = 1; off < NSCB; off <<= 1) {
        int add = (t >= off) ? sm[t - off] : 0;
        __syncthreads();
        sm[t] += add;
        __syncthreads();
    }
    g_part[t] = sm[t] - v;                   // exclusive block base
}

__global__ void __launch_bounds__(256) k_scanC() {     // add block bases, init cursors
    const int i = blockIdx.x * 256 + threadIdx.x;
    int s = g_cstart[i] + g_part[blockIdx.x];
    g_cstart[i] = s;
    g_cur[i] = s;
}

__global__ void __launch_bounds__(256) k_fill(const float* __restrict__ x) {
    const int p = blockIdx.x * 256 + threadIdx.x;
    const int n = p & (NPT - 1);                          // within-batch index
    int cid = g_pcid[p];
    int slot = atomicAdd(&g_cur[cid], 1);
    g_pts4[slot] = make_float4(x[3*p], x[3*p+1], x[3*p+2], __int_as_float(n));
}

// ---------------- kernel: grid 9-NN (row-run phase A + rare ring fallback) --------
__global__ void __launch_bounds__(256) knn_grid() {
    const int s = blockIdx.x * 256 + threadIdx.x;        // cell-sorted slot
    const int b = s >> 13;
    float4 me = g_pts4[s];
    const float qx = me.x, qy = me.y, qz = me.z;
    const int n = __float_as_int(me.w);
    const float ax = -2.0f * qx, ay = -2.0f * qy, az = -2.0f * qz;
    const float qsq = fmaf(qx, qx, fmaf(qy, qy, qz * qz));

    const int cx = cellc(qx), cy = cellc(qy), cz = cellc(qz);
    const int cb = b * GC;

    float dist[KNB];
#pragma unroll
    for (int j = 0; j < KNB; ++j) dist[j] = INF_F;
    float thr = INF_F;
    int cnt = 0;
    const int p = b * NPT + n;
    float2* lg = g_log + (size_t)p * LOGCAP;

    // ---- phase A: 3x3x3 neighborhood as up-to-9 contiguous x-row runs ----
    const int x0 = max(cx - 1, 0), x1 = min(cx + 1, G - 1);
    const int y0 = max(cy - 1, 0), y1 = min(cy + 1, G - 1);
    const int z0 = max(cz - 1, 0), z1 = min(cz + 1, G - 1);
    int rs[9], re[9], nr = 0;
#pragma unroll 3
    for (int zc = z0; zc <= z1; ++zc)
#pragma unroll 3
        for (int yc = y0; yc <= y1; ++yc) {
            int rowc = cb + (zc * G + yc) * G;
            rs[nr] = g_cstart[rowc + x0];                     // independent loads, MLP
            re[nr] = g_cstart[rowc + x1] + g_cnt[rowc + x1];
            ++nr;
        }
    for (int rrow = 0; rrow < nr; ++rrow) {
        int en = re[rrow];
        for (int i = rs[rrow]; i < en; ++i) {
            float4 c = g_pts4[i];
            float d = fmaf(c.z, c.z + az, fmaf(c.y, c.y + ay, c.x * (c.x + ax)));
            int mi = __float_as_int(c.w);
            if (d < thr && mi != n) {
                int w = (cnt < LOGCAP) ? cnt : (LOGCAP - 1);
                lg[w] = make_float2(d, c.w);
                ++cnt;
                dchain(dist, d);
                thr = dist[KNB-1];
            }
        }
    }

    // termination bound for the r=1 box
    bool done = false;
    if (dist[KNB-1] < INF_F) {
        float face = INF_F;
        if (cx - 1 > 0)     face = fminf(face, qx - (BOXLO + (cx - 1) * CS));
        if (cx + 1 < G - 1) face = fminf(face, (BOXLO + (cx + 2) * CS) - qx);
        if (cy - 1 > 0)     face = fminf(face, qy - (BOXLO + (cy - 1) * CS));
        if (cy + 1 < G - 1) face = fminf(face, (BOXLO + (cy + 2) * CS) - qy);
        if (cz - 1 > 0)     face = fminf(face, qz - (BOXLO + (cz - 1) * CS));
        if (cz + 1 < G - 1) face = fminf(face, (BOXLO + (cz + 2) * CS) - qz);
        float d9sq = dist[KNB-1] + qsq;
        if (d9sq + 1.0e-4f <= face * face) done = true;
    }

    // ---- phase B (rare): generic ring expansion from r=2 ----
    for (int r = 2; r <= G && !done; ++r) {
        for (int dz = -r; dz <= r; ++dz) {
            int zc = cz + dz;
            if (zc < 0 || zc >= G) continue;
            bool zface = (dz == -r || dz == r);
            for (int dy = -r; dy <= r; ++dy) {
                int yc = cy + dy;
                if (yc < 0 || yc >= G) continue;
                bool yface = (dy == -r || dy == r);
                int dxstep = (zface || yface) ? 1 : 2 * r;
                for (int dx = -r; dx <= r; dx += dxstep) {
                    int xc = cx + dx;
                    if (xc < 0 || xc >= G) continue;
                    int cid = cb + (zc * G + yc) * G + xc;
                    int st = g_cstart[cid];
                    int en = st + g_cnt[cid];
                    for (int i = st; i < en; ++i) {
                        float4 c = g_pts4[i];
                        float d = fmaf(c.z, c.z + az, fmaf(c.y, c.y + ay, c.x * (c.x + ax)));
                        int mi = __float_as_int(c.w);
                        if (d < thr && mi != n) {
                            int w = (cnt < LOGCAP) ? cnt : (LOGCAP - 1);
                            lg[w] = make_float2(d, c.w);
                            ++cnt;
                            dchain(dist, d);
                            thr = dist[KNB-1];
                        }
                    }
                }
            }
        }
        if (dist[KNB-1] < INF_F) {
            float face = INF_F;
            if (cx - r > 0)     face = fminf(face, qx - (BOXLO + (cx - r) * CS));
            if (cx + r < G - 1) face = fminf(face, (BOXLO + (cx + r + 1) * CS) - qx);
            if (cy - r > 0)     face = fminf(face, qy - (BOXLO + (cy - r) * CS));
            if (cy + r < G - 1) face = fminf(face, (BOXLO + (cy + r + 1) * CS) - qy);
            if (cz - r > 0)     face = fminf(face, qz - (BOXLO + (cz - r) * CS));
            if (cz + r < G - 1) face = fminf(face, (BOXLO + (cz + r + 1) * CS) - qz);
            float d9sq = dist[KNB-1] + qsq;
            if (d9sq + 1.0e-4f <= face * face) done = true;
        }
    }

    g_lcnt[p] = (cnt < LOGCAP) ? cnt : LOGCAP;
#pragma unroll
    for (int j = 0; j < KNB; ++j) g_pd[p * KNB + j] = dist[j];
}

// ---------------- block reduction of 14 partial sums -> global atomics ----------------
__device__ __forceinline__ void block_reduce_14(float* v, float* dst1, float* dst2) {
    __shared__ float red[8 * 14];
    const int lane = threadIdx.x & 31, w = threadIdx.x >> 5;
#pragma unroll
    for (int i = 0; i < 14; ++i) {
        float t = v[i];
        t += __shfl_down_sync(0xffffffffu, t, 16);
        t += __shfl_down_sync(0xffffffffu, t, 8);
        t += __shfl_down_sync(0xffffffffu, t, 4);
        t += __shfl_down_sync(0xffffffffu, t, 2);
        t += __shfl_down_sync(0xffffffffu, t, 1);
        v[i] = t;
    }
    if (lane == 0) {
#pragma unroll
        for (int i = 0; i < 14; ++i) red[w * 14 + i] = v[i];
    }
    __syncthreads();
    if (threadIdx.x < 14) {
        float t = 0.f;
#pragma unroll
        for (int ww = 0; ww < 8; ++ww) t += red[ww * 14 + threadIdx.x];
        if (threadIdx.x < CH) atomicAdd(&dst1[threadIdx.x], t);
        else                  atomicAdd(&dst2[threadIdx.x - CH], t);
    }
}

// ---------------- kernel: index claim + features + MLP1 + BN1 stats --------
__global__ void __launch_bounds__(256) feat_kernel(const float* __restrict__ x,
                                                   const float* __restrict__ w1) {
    __shared__ float w1s[CH * CH];
    if (threadIdx.x < CH * CH) w1s[threadIdx.x] = w1[threadIdx.x];
    __syncthreads();

    const int p = blockIdx.x * 256 + threadIdx.x;     // 0..NPTS-1
    const int b = p >> 13;
    const int n = p & (NPT - 1);

    float dm[KNB];
#pragma unroll
    for (int j = 0; j < KNB; ++j) dm[j] = g_pd[p * KNB + j];

    // claim indices: scan log in order; leftmost-unclaimed-equal == top_k tie-break
    int idx[KNB];
#pragma unroll
    for (int j = 0; j < KNB; ++j) idx[j] = n;         // safe default
    unsigned claimed = 0;
    const float dmax = dm[KNB-1];
    const float2* L = g_log + (size_t)p * LOGCAP;
    const int cn = g_lcnt[p];
    for (int k = 0; k < cn; ++k) {
        float2 e = L[k];
        if (e.x <= dmax) {
            bool donec = false;
#pragma unroll
            for (int j = 0; j < KNB; ++j) {
                bool m = (!donec) && (dm[j] == e.x) && !((claimed >> j) & 1u);
                if (m) { idx[j] = __float_as_int(e.y); claimed |= (1u << j); donec = true; }
            }
        }
    }

    const float* xb = x + b * (NPT * 3);
    const float qx = xb[3*n], qy = xb[3*n+1], qz = xb[3*n+2];

    float vx[KNB], vy[KNB], vz[KNB], ph[KNB];
#pragma unroll
    for (int j = 0; j < KNB; ++j) {
        int mi = idx[j];
        vx[j] = xb[3*mi]   - qx;
        vy[j] = xb[3*mi+1] - qy;
        vz[j] = xb[3*mi+2] - qz;
        ph[j] = atan2f(vy[j], vx[j]);   // monotone in reference's phi
    }
    // stable unrolled insertion sort by phi ascending (registers only)
#pragma unroll
    for (int i = 1; i < KNB; ++i)
#pragma unroll
        for (int j = i; j > 0; --j)
            if (ph[j] < ph[j-1]) {
                float t;
                t = ph[j]; ph[j] = ph[j-1]; ph[j-1] = t;
                t = vx[j]; vx[j] = vx[j-1]; vx[j-1] = t;
                t = vy[j]; vy[j] = vy[j-1]; vy[j-1] = t;
                t = vz[j]; vz[j] = vz[j-1]; vz[j-1] = t;
            }

    float mask = 1.0f;
    float vals[2 * CH];
#pragma unroll
    for (int i = 0; i < 2 * CH; ++i) vals[i] = 0.f;

#pragma unroll
    for (int j = 0; j < KNB; ++j) {
        const int j2 = (j + 1 == KNB) ? 0 : (j + 1);
        float axv = vx[j],  ayv = vy[j],  azv = vz[j];
        float bxv = vx[j2], byv = vy[j2], bzv = vz[j2];
        float cx = 0.5f * (axv + bxv), cy = 0.5f * (ayv + byv), cz = 0.5f * (azv + bzv);
        float nx = fmaf(ayv, bzv, -azv * byv) + 1e-5f;
        float ny = fmaf(azv, bxv, -axv * bzv) + 1e-5f;
        float nz = fmaf(axv, byv, -ayv * bxv) + 1e-5f;
        float inv = rsqrtf(fmaf(nx, nx, fmaf(ny, ny, nz * nz)));
        nx *= inv; ny *= inv; nz *= inv;
        if (j == 0) mask = (nx > 0.f) ? 1.f : -1.f;
        nx *= mask; ny *= mask; nz *= mask;
        float pos = fmaf(cx, nx, fmaf(cy, ny, cz * nz)) * 0.57735026918962576f; // /sqrt(3)
        float f[CH] = {cx, cy, cz, nx, ny, nz, pos};
        float h[CH];
#pragma unroll
        for (int o = 0; o < CH; ++o) {
            float acc = 0.f;
#pragma unroll
            for (int c = 0; c < CH; ++c) acc = fmaf(f[c], w1s[o * CH + c], acc);
            h[o] = acc;
            vals[o] += acc;
            vals[CH + o] = fmaf(acc, acc, vals[CH + o]);
        }
        const int r = p * KNB + j;
        g_h[2*r]     = make_float4(h[0], h[1], h[2], h[3]);
        g_h[2*r + 1] = make_float4(h[4], h[5], h[6], 0.f);
    }
    block_reduce_14(vals, g_sum1, g_sq1);
}

// ---------------- relu(bn1) -> MLP2 (+bias) in place, BN2 stats ----------
__global__ void __launch_bounds__(256) mlp2_kernel(const float* __restrict__ w2,
                                                   const float* __restrict__ bias2,
                                                   const float* __restrict__ gamma1,
                                                   const float* __restrict__ beta1) {
    __shared__ float w2s[CH * CH], cb[CH], aff[2 * CH];
    const int t = threadIdx.x;
    if (t < CH * CH) w2s[t] = w2[t];
    if (t < CH)      cb[t]  = bias2[t];
    if (t < CH) {
        const float invN = 1.0f / (float)NROWS;
        float m = g_sum1[t] * invN;
        float v = g_sq1[t] * invN - m * m;
        float sc = gamma1[t] * rsqrtf(v + 1e-5f);
        aff[t] = sc;
        aff[CH + t] = fmaf(-m, sc, beta1[t]);
    }
    __syncthreads();

    const int r = blockIdx.x * 256 + t;    // < NROWS (exact)
    float4 h0 = g_h[2*r], h1 = g_h[2*r + 1];
    float hv[CH] = {h0.x, h0.y, h0.z, h0.w, h1.x, h1.y, h1.z};
    float a[CH];
#pragma unroll
    for (int c = 0; c < CH; ++c) a[c] = fmaxf(fmaf(hv[c], aff[c], aff[CH + c]), 0.f);
    float vals[2 * CH];
#pragma unroll
    for (int o = 0; o < CH; ++o) {
        float acc = cb[o];
#pragma unroll
        for (int c = 0; c < CH; ++c) acc = fmaf(a[c], w2s[o * CH + c], acc);
        vals[o] = acc;
        vals[CH + o] = acc * acc;
    }
    g_h[2*r]     = make_float4(vals[0], vals[1], vals[2], vals[3]);
    g_h[2*r + 1] = make_float4(vals[4], vals[5], vals[6], 0.f);
    block_reduce_14(vals, g_sum2, g_sq2);
}

// ---------------- relu(bn2) -> MLP3 (+bias) -> max over K -> concat -------
__global__ void __launch_bounds__(256) out_kernel(const float* __restrict__ x,
                                                  const float* __restrict__ w3,
                                                  const float* __restrict__ bias3,
                                                  const float* __restrict__ gamma2,
                                                  const float* __restrict__ beta2,
                                                  float* __restrict__ out) {
    __shared__ float w3s[CH * CH], cb[CH], aff[2 * CH];
    const int t = threadIdx.x;
    if (t < CH * CH) w3s[t] = w3[t];
    if (t < CH)      cb[t]  = bias3[t];
    if (t < CH) {
        const float invN = 1.0f / (float)NROWS;
        float m = g_sum2[t] * invN;
        float v = g_sq2[t] * invN - m * m;
        float sc = gamma2[t] * rsqrtf(v + 1e-5f);
        aff[t] = sc;
        aff[CH + t] = fmaf(-m, sc, beta2[t]);
    }
    __syncthreads();

    const int p = blockIdx.x * 256 + t;    // point id
    float best[CH];
#pragma unroll
    for (int o = 0; o < CH; ++o) best[o] = -INF_F;

#pragma unroll
    for (int j = 0; j < KNB; ++j) {
        const int r = p * KNB + j;
        float4 h0 = g_h[2*r], h1 = g_h[2*r + 1];
        float hv[CH] = {h0.x, h0.y, h0.z, h0.w, h1.x, h1.y, h1.z};
        float a[CH];
#pragma unroll
        for (int c = 0; c < CH; ++c) a[c] = fmaxf(fmaf(hv[c], aff[c], aff[CH + c]), 0.f);
#pragma unroll
        for (int o = 0; o < CH; ++o) {
            float acc = cb[o];
#pragma unroll
            for (int c = 0; c < CH; ++c) acc = fmaf(a[c], w3s[o * CH + c], acc);
            best[o] = fmaxf(best[o], acc);
        }
    }
    float* orow = out + p * 10;
    orow[0] = x[p*3]; orow[1] = x[p*3+1]; orow[2] = x[p*3+2];
#pragma unroll
    for (int o = 0; o < CH; ++o) orow[3 + o] = best[o];
}

// ---------------- launch ----------------
extern "C" void kernel_launch(void* const* d_in, const int* in_sizes, int n_in,
                              void* d_out, int out_size) {
    const float* x      = (const float*)d_in[0];
    const float* w1     = (const float*)d_in[1];
    const float* gamma1 = (const float*)d_in[2];
    const float* beta1  = (const float*)d_in[3];
    const float* w2     = (const float*)d_in[4];
    const float* bias2  = (const float*)d_in[5];
    const float* gamma2 = (const float*)d_in[6];
    const float* beta2  = (const float*)d_in[7];
    const float* w3     = (const float*)d_in[8];
    const float* bias3  = (const float*)d_in[9];
    float* out = (float*)d_out;

    k_zero<<<TC / 256, 256>>>();
    k_count<<<NPTS / 256, 256>>>(x);
    k_scanA<<<NSCB, 256>>>();
    k_scanB<<<1, NSCB>>>();
    k_scanC<<<NSCB, 256>>>();
    k_fill<<<NPTS / 256, 256>>>(x);
    knn_grid<<<NPTS / 256, 256>>>();
    feat_kernel<<<NPTS / 256, 256>>>(x, w1);
    mlp2_kernel<<<NROWS / 256, 256>>>(w2, bias2, gamma1, beta1);
    out_kernel<<<NPTS / 256, 256>>>(x, w3, bias3, gamma2, beta2, out);
}